// round 3
// baseline (speedup 1.0000x reference)
#include <cuda_runtime.h>
#include <cuda_bf16.h>
#include <math.h>

#define Bq 16
#define Sq 512
#define Dq 128
#define Hq 8
#define DKq 16
#define TOK (Bq*Sq)           // 8192
#define ELEMS (TOK*Dq)        // 1048576

// ---------------- scratch (no allocation allowed) ----------------
__device__ float g_h[ELEMS];
__device__ float g_a[ELEMS];
__device__ float g_q[ELEMS];
__device__ float g_k[ELEMS];
__device__ float g_v[ELEMS];
__device__ float g_w2[3*Dq*Dq];

// ---------------- x + positional signal ----------------
__global__ void addpos_kernel(const float* __restrict__ x, float* __restrict__ out) {
    int idx = blockIdx.x * 256 + threadIdx.x;
    if (idx >= ELEMS) return;
    int d = idx & 127;
    int s = (idx >> 7) & 511;
    const float inc = 0.14619588050756158f; // log(10000)/63
    int dd = (d < 64) ? d : (d - 64);
    float inv = expf(-inc * (float)dd);
    float a = (float)s * inv;
    float p = (d < 64) ? sinf(a) : cosf(a);
    out[idx] = x[idx] + p;
}

// ---------------- layernorm: 1 block (128 thr) per token ----------------
__global__ void ln_kernel(const float* __restrict__ x, float* __restrict__ y,
                          const float* __restrict__ g, const float* __restrict__ b) {
    int t = blockIdx.x;
    int d = threadIdx.x;
    float v = x[t*Dq + d];
    float s = v, s2 = v*v;
    #pragma unroll
    for (int o = 16; o > 0; o >>= 1) {
        s  += __shfl_xor_sync(0xffffffffu, s,  o);
        s2 += __shfl_xor_sync(0xffffffffu, s2, o);
    }
    __shared__ float ss[4], ss2[4];
    int w = d >> 5;
    if ((d & 31) == 0) { ss[w] = s; ss2[w] = s2; }
    __syncthreads();
    s  = ss[0] + ss[1] + ss[2] + ss[3];
    s2 = ss2[0] + ss2[1] + ss2[2] + ss2[3];
    float mu  = s  * (1.0f/128.0f);
    float var = s2 * (1.0f/128.0f) - mu*mu;
    float rs = rsqrtf(var + 1e-5f);
    y[t*Dq + d] = (v - mu) * rs * g[d] + b[d];
}

// ---------------- depthwise conv (K=7, pad=3) + bias ----------------
__global__ void dwconv_kernel(const float* __restrict__ h, float* __restrict__ y,
                              const float* __restrict__ w, const float* __restrict__ bias) {
    int idx = blockIdx.x * 256 + threadIdx.x;
    if (idx >= ELEMS) return;
    int d = idx & 127;
    int s = (idx >> 7) & 511;
    int bb = idx >> 16;
    float acc = bias[d];
    #pragma unroll
    for (int kk = 0; kk < 7; kk++) {
        int ss = s + kk - 3;
        if (ss >= 0 && ss < 512)
            acc += h[(bb*512 + ss)*Dq + d] * __ldg(&w[d*7 + kk]);
    }
    y[idx] = acc;
}

// ---------------- generic token GEMM: out[m,n] = sum_k A[m,k] * W(k,n) ----------------
// WNK: weight stored [N,K] (row n contiguous in k). otherwise [K,N].
// BIAS_MODE: 0 none, 1 per-n vector, 2 scalar bias[0].
template<bool WNK, int BIAS_MODE, bool RELU, bool HAS_RES>
__global__ void gemm128(const float* __restrict__ A, const float* __restrict__ W,
                        const float* __restrict__ bias, const float* __restrict__ res,
                        float* __restrict__ out) {
    __shared__ float As[64][33];
    __shared__ float Ws[32][129];
    int m0 = blockIdx.x * 64;
    int tid = threadIdx.x;
    int ty = tid >> 4, tx = tid & 15;
    float acc[4][8];
    #pragma unroll
    for (int i = 0; i < 4; i++)
        #pragma unroll
        for (int j = 0; j < 8; j++) acc[i][j] = 0.f;

    for (int kb = 0; kb < 128; kb += 32) {
        #pragma unroll
        for (int i = 0; i < 8; i++) {
            int idx = i*256 + tid;
            int r = idx >> 5, c = idx & 31;
            As[r][c] = A[(m0 + r)*128 + kb + c];
        }
        #pragma unroll
        for (int i = 0; i < 16; i++) {
            int idx = i*256 + tid;
            if (WNK) {
                int n = idx >> 5, c = idx & 31;
                Ws[c][n] = W[n*128 + kb + c];
            } else {
                int k = idx >> 7, n = idx & 127;
                Ws[k][n] = W[(kb + k)*128 + n];
            }
        }
        __syncthreads();
        #pragma unroll
        for (int k = 0; k < 32; k++) {
            float a[4], b[8];
            #pragma unroll
            for (int j = 0; j < 4; j++) a[j] = As[ty*4 + j][k];
            #pragma unroll
            for (int j = 0; j < 8; j++) b[j] = Ws[k][tx + 16*j];
            #pragma unroll
            for (int i = 0; i < 4; i++)
                #pragma unroll
                for (int j = 0; j < 8; j++) acc[i][j] += a[i]*b[j];
        }
        __syncthreads();
    }
    float bb = (BIAS_MODE == 2) ? bias[0] : 0.f;
    #pragma unroll
    for (int i = 0; i < 4; i++) {
        int m = m0 + ty*4 + i;
        #pragma unroll
        for (int j = 0; j < 8; j++) {
            int n = tx + 16*j;
            float v = acc[i][j];
            if (BIAS_MODE == 1) v += bias[n];
            if (BIAS_MODE == 2) v += bb;
            if (RELU) v = fmaxf(v, 0.f);
            if (HAS_RES) v += res[m*128 + n];
            out[m*128 + n] = v;
        }
    }
}

// ---------------- repack Wq/Wk/Wv (H,D,DK) -> [D, N=h*16+k] ----------------
__global__ void repack_qkv(const float* __restrict__ Wq, const float* __restrict__ Wk,
                           const float* __restrict__ Wv, float* __restrict__ w2) {
    int idx = blockIdx.x * 256 + threadIdx.x;
    if (idx >= Dq*Dq) return;
    int d = idx >> 7;
    int n = idx & 127;
    int h = n >> 4;
    int kk = n & 15;
    int src = h*Dq*DKq + d*DKq + kk;
    w2[idx]             = Wq[src];
    w2[Dq*Dq + idx]     = Wk[src];
    w2[2*Dq*Dq + idx]   = Wv[src];
}

// ---------------- attention: one block per (b,h), K/V in smem ----------------
__global__ void attn_kernel(const float* __restrict__ q, const float* __restrict__ k,
                            const float* __restrict__ v, const int* __restrict__ mask,
                            float* __restrict__ out) {
    extern __shared__ float sm[];
    float* Ks = sm;              // 512*16
    float* Vs = sm + 8192;       // 512*16
    float* Ms = sm + 16384;      // 512
    int b = blockIdx.x >> 3;
    int h = blockIdx.x & 7;
    int tid = threadIdx.x;

    for (int idx = tid; idx < 8192; idx += 256) {
        int t = idx >> 4, c = idx & 15;
        int g = (b*512 + t)*Dq + h*16 + c;
        Ks[idx] = k[g];
        Vs[idx] = v[g];
    }
    for (int t = tid; t < 512; t += 256)
        Ms[t] = mask[b*512 + t] ? 0.f : -1e30f;
    __syncthreads();

    for (int s = tid; s < 512; s += 256) {
        float qr[16];
        #pragma unroll
        for (int c = 0; c < 16; c++) qr[c] = q[(b*512 + s)*Dq + h*16 + c];

        float mx = -1e30f;
        for (int t = 0; t < 512; t++) {
            float sc = 0.f;
            #pragma unroll
            for (int c = 0; c < 16; c++) sc += qr[c] * Ks[t*16 + c];
            sc = sc * 0.25f + Ms[t];
            mx = fmaxf(mx, sc);
        }
        float sum = 0.f;
        float o[16];
        #pragma unroll
        for (int c = 0; c < 16; c++) o[c] = 0.f;
        for (int t = 0; t < 512; t++) {
            float sc = 0.f;
            #pragma unroll
            for (int c = 0; c < 16; c++) sc += qr[c] * Ks[t*16 + c];
            sc = sc * 0.25f + Ms[t];
            float p = __expf(sc - mx);
            sum += p;
            #pragma unroll
            for (int c = 0; c < 16; c++) o[c] += p * Vs[t*16 + c];
        }
        float inv = 1.f / sum;
        #pragma unroll
        for (int c = 0; c < 16; c++)
            out[(b*512 + s)*Dq + h*16 + c] = o[c] * inv;
    }
}

// ---------------- launch ----------------
extern "C" void kernel_launch(void* const* d_in, const int* in_sizes, int n_in,
                              void* d_out, int out_size) {
    const float* x     = (const float*)d_in[0];
    const int*   mask  = (const int*)  d_in[1];
    const float* ln_s  = (const float*)d_in[2];
    const float* ln_b  = (const float*)d_in[3];
    const float* dw_w  = (const float*)d_in[4];
    const float* dw_b  = (const float*)d_in[5];
    const float* pw_w  = (const float*)d_in[6];
    const float* pw_b  = (const float*)d_in[7];
    const float* Wq    = (const float*)d_in[8];
    const float* Wk    = (const float*)d_in[9];
    const float* Wv    = (const float*)d_in[10];
    const float* Wo    = (const float*)d_in[11];
    const float* ab    = (const float*)d_in[12];
    const float* f1w   = (const float*)d_in[13];
    const float* f1b   = (const float*)d_in[14];
    const float* f2w   = (const float*)d_in[15];
    const float* f2b   = (const float*)d_in[16];
    float* out = (float*)d_out;

    float *hP, *aP, *qP, *kP, *vP, *w2P;
    cudaGetSymbolAddress((void**)&hP, g_h);
    cudaGetSymbolAddress((void**)&aP, g_a);
    cudaGetSymbolAddress((void**)&qP, g_q);
    cudaGetSymbolAddress((void**)&kP, g_k);
    cudaGetSymbolAddress((void**)&vP, g_v);
    cudaGetSymbolAddress((void**)&w2P, g_w2);

    const int ATTN_SMEM = (8192 + 8192 + 512) * 4;
    cudaFuncSetAttribute(attn_kernel, cudaFuncAttributeMaxDynamicSharedMemorySize, ATTN_SMEM);

    // out = x + pos
    addpos_kernel<<<ELEMS/256, 256>>>(x, out);

    // conv stack
    for (int i = 0; i < 4; i++) {
        ln_kernel<<<TOK, 128>>>(out, hP, ln_s + i*Dq, ln_b + i*Dq);
        dwconv_kernel<<<ELEMS/256, 256>>>(hP, aP, dw_w + i*Dq*7, dw_b + i*Dq);
        // pointwise + bias + relu + residual (in-place on out)
        gemm128<true, 1, true, true><<<TOK/64, 256>>>(aP, pw_w + i*Dq*Dq, pw_b + i*Dq, out, out);
    }

    // attention
    ln_kernel<<<TOK, 128>>>(out, hP, ln_s + 4*Dq, ln_b + 4*Dq);
    repack_qkv<<<(Dq*Dq + 255)/256, 256>>>(Wq, Wk, Wv, w2P);
    gemm128<false, 2, false, false><<<TOK/64, 256>>>(hP, w2P,             ab, nullptr, qP);
    gemm128<false, 2, false, false><<<TOK/64, 256>>>(hP, w2P + Dq*Dq,     ab, nullptr, kP);
    gemm128<false, 2, false, false><<<TOK/64, 256>>>(hP, w2P + 2*Dq*Dq,   ab, nullptr, vP);
    attn_kernel<<<Bq*Hq, 256, ATTN_SMEM>>>(qP, kP, vP, mask, aP);
    gemm128<false, 2, false, true><<<TOK/64, 256>>>(aP, Wo, ab, out, out);

    // feed-forward
    ln_kernel<<<TOK, 128>>>(out, hP, ln_s + 5*Dq, ln_b + 5*Dq);
    gemm128<true, 1, true,  false><<<TOK/64, 256>>>(hP, f1w, f1b, nullptr, aP);
    gemm128<true, 1, false, true ><<<TOK/64, 256>>>(aP, f2w, f2b, out, out);
}

// round 4
// speedup vs baseline: 1.7436x; 1.7436x over previous
#include <cuda_runtime.h>
#include <math.h>

#define TOKS 8192
#define ELEMS 1048576

// ---------------- scratch ----------------
__device__ float g_h[ELEMS];
__device__ float g_h2[ELEMS];
__device__ float g_a[ELEMS];
__device__ float g_qkv[3*ELEMS];
__device__ float g_wT[9*16384];   // [0..2] qkv, [3..6] pw, [7] f1, [8] f2  (all [K][N])

// ---------------- weight prep: repack/transpose everything to [K=128][N=128] ----------------
__global__ void prep_weights(const float* __restrict__ Wq, const float* __restrict__ Wk,
                             const float* __restrict__ Wv, const float* __restrict__ pw,
                             const float* __restrict__ f1, const float* __restrict__ f2,
                             float* __restrict__ wT) {
    int idx = blockIdx.x*256 + threadIdx.x;          // 9*16384
    if (idx >= 9*16384) return;
    int j = idx >> 14, r = idx & 16383;
    int d = r >> 7, n = r & 127;
    float v;
    if (j < 3) {
        const float* W = (j==0) ? Wq : (j==1) ? Wk : Wv;   // (H,128,16)
        v = W[(n>>4)*2048 + d*16 + (n&15)];
    } else if (j < 7) {
        v = pw[(j-3)*16384 + n*128 + d];                    // (D_out, D_in) -> [in][out]
    } else {
        const float* W = (j==7) ? f1 : f2;
        v = W[n*128 + d];                                    // f_w.T
    }
    wT[idx] = v;
}

// ---------------- addpos + LN0 : out = x+pos, h = LN(out) ----------------
__global__ __launch_bounds__(512) void addpos_ln(const float* __restrict__ x,
                                                 float* __restrict__ out, float* __restrict__ hout,
                                                 const float* __restrict__ lnS,
                                                 const float* __restrict__ lnB) {
    int m0 = blockIdx.x * 64;
    int lane = threadIdx.x & 31, warp = threadIdx.x >> 5;
    int col = lane * 4;
    const float inc = 0.14619588050756158f;   // log(10000)/63
    float4 g4 = *(const float4*)&lnS[col];
    float4 b4 = *(const float4*)&lnB[col];
    #pragma unroll
    for (int i = 0; i < 4; i++) {
        int m = m0 + warp*4 + i;
        int s = m & 511;
        float4 xv = *(const float4*)&x[m*128 + col];
        float v[4] = {xv.x, xv.y, xv.z, xv.w};
        #pragma unroll
        for (int jj = 0; jj < 4; jj++) {
            int d = col + jj;
            int dd = d & 63;
            float a = (float)s * expf(-inc*(float)dd);
            v[jj] += (d < 64) ? sinf(a) : cosf(a);
        }
        float rs_ = v[0]+v[1]+v[2]+v[3];
        float rq  = v[0]*v[0]+v[1]*v[1]+v[2]*v[2]+v[3]*v[3];
        #pragma unroll
        for (int o = 16; o > 0; o >>= 1) {
            rs_ += __shfl_xor_sync(0xffffffffu, rs_, o);
            rq  += __shfl_xor_sync(0xffffffffu, rq,  o);
        }
        float mu  = rs_ * (1.0f/128.0f);
        float var = rq  * (1.0f/128.0f) - mu*mu;
        float rinv = rsqrtf(var + 1e-5f);
        float4 ov = {v[0], v[1], v[2], v[3]};
        *(float4*)&out[m*128 + col] = ov;
        float4 hv;
        hv.x = (v[0]-mu)*rinv*g4.x + b4.x;
        hv.y = (v[1]-mu)*rinv*g4.y + b4.y;
        hv.z = (v[2]-mu)*rinv*g4.z + b4.z;
        hv.w = (v[3]-mu)*rinv*g4.w + b4.w;
        *(float4*)&hout[m*128 + col] = hv;
    }
}

// ---------------- fused GEMM: [64xM tile] x [128K x 128N], 512 threads ----------------
// DW: A-tile = depthwise-conv7(A=h) + dwb.  MULTI: batched over blockIdx.y (QKV).
// BIASM: 1 per-n vector, 2 scalar bias[0].  LN: epilogue layernorm -> hout.
template<bool DW, bool MULTI, int BIASM, bool RELU, bool RES, bool LN>
__global__ __launch_bounds__(512) void gemmF(
    const float* __restrict__ A, const float* __restrict__ W,
    const float* __restrict__ bias, const float* __restrict__ res,
    float* __restrict__ out, float* __restrict__ hout,
    const float* __restrict__ lnS, const float* __restrict__ lnB,
    const float* __restrict__ dww, const float* __restrict__ dwb)
{
    extern __shared__ float sm[];
    float (*As)[128] = (float(*)[128])sm;            // 64 x 128 (m-major)
    float (*Ws)[128] = (float(*)[128])(sm + 64*128); // 128 x 128 (k-major)
    if (MULTI) { W += blockIdx.y * 16384; out += (size_t)blockIdx.y * ELEMS; }

    int m0 = blockIdx.x * 64;
    int t = threadIdx.x;
    int lane = t & 31, warp = t >> 5;

    // load W (k = warp*8+p, n4 = lane*4): coalesced, conflict-free
    #pragma unroll
    for (int p = 0; p < 8; p++) {
        int k = warp*8 + p;
        *(float4*)&Ws[k][lane*4] = *(const float4*)&W[k*128 + lane*4];
    }

    if (DW) {
        // thread: channel d = t&127, token quarter q = t>>7 (16 tokens each)
        int d = t & 127, q = t >> 7;
        float wr[7];
        #pragma unroll
        for (int kk = 0; kk < 7; kk++) wr[kk] = dww[d*7 + kk];
        float db = dwb[d];
        int sBase = (m0 & 511) + q*16;
        const float* hb = A + (size_t)(m0 & ~511) * 128;
        float hwin[22];
        #pragma unroll
        for (int jj = 0; jj < 22; jj++) {
            int s = sBase + jj - 3;
            hwin[jj] = (s >= 0 && s < 512) ? hb[s*128 + d] : 0.f;
        }
        #pragma unroll
        for (int i = 0; i < 16; i++) {
            float acc = db;
            #pragma unroll
            for (int kk = 0; kk < 7; kk++) acc += wr[kk] * hwin[i+kk];
            As[q*16 + i][d] = acc;
        }
    } else {
        #pragma unroll
        for (int p = 0; p < 4; p++) {
            int m = warp*4 + p;
            *(float4*)&As[m][lane*4] = *(const float4*)&A[(size_t)(m0+m)*128 + lane*4];
        }
    }
    __syncthreads();

    float acc[4][4] = {};
    int row0 = warp*4, col = lane*4;
    #pragma unroll 4
    for (int k = 0; k < 128; k += 2) {
        float4 b0 = *(const float4*)&Ws[k][col];
        float4 b1 = *(const float4*)&Ws[k+1][col];
        #pragma unroll
        for (int i = 0; i < 4; i++) {
            float2 a2 = *(const float2*)&As[row0+i][k];
            acc[i][0] += a2.x*b0.x; acc[i][1] += a2.x*b0.y;
            acc[i][2] += a2.x*b0.z; acc[i][3] += a2.x*b0.w;
            acc[i][0] += a2.y*b1.x; acc[i][1] += a2.y*b1.y;
            acc[i][2] += a2.y*b1.z; acc[i][3] += a2.y*b1.w;
        }
    }

    // epilogue
    float4 bv = {0,0,0,0};
    if (BIASM == 1) bv = *(const float4*)&bias[col];
    float bs = (BIASM == 2) ? bias[0] : 0.f;
    float4 g4 = {0,0,0,0}, lb4 = {0,0,0,0};
    if (LN) { g4 = *(const float4*)&lnS[col]; lb4 = *(const float4*)&lnB[col]; }

    #pragma unroll
    for (int i = 0; i < 4; i++) {
        int m = m0 + row0 + i;
        float v[4];
        #pragma unroll
        for (int jj = 0; jj < 4; jj++) {
            float val = acc[i][jj];
            if (BIASM == 1) val += ((const float*)&bv)[jj];
            if (BIASM == 2) val += bs;
            if (RELU) val = fmaxf(val, 0.f);
            v[jj] = val;
        }
        if (RES) {
            float4 r4 = *(const float4*)&res[(size_t)m*128 + col];
            v[0] += r4.x; v[1] += r4.y; v[2] += r4.z; v[3] += r4.w;
        }
        float4 ov = {v[0], v[1], v[2], v[3]};
        *(float4*)&out[(size_t)m*128 + col] = ov;
        if (LN) {
            float rs_ = v[0]+v[1]+v[2]+v[3];
            float rq  = v[0]*v[0]+v[1]*v[1]+v[2]*v[2]+v[3]*v[3];
            #pragma unroll
            for (int o = 16; o > 0; o >>= 1) {
                rs_ += __shfl_xor_sync(0xffffffffu, rs_, o);
                rq  += __shfl_xor_sync(0xffffffffu, rq,  o);
            }
            float mu  = rs_ * (1.0f/128.0f);
            float var = rq  * (1.0f/128.0f) - mu*mu;
            float rinv = rsqrtf(var + 1e-5f);
            float4 hv;
            hv.x = (v[0]-mu)*rinv*g4.x + lb4.x;
            hv.y = (v[1]-mu)*rinv*g4.y + lb4.y;
            hv.z = (v[2]-mu)*rinv*g4.z + lb4.z;
            hv.w = (v[3]-mu)*rinv*g4.w + lb4.w;
            *(float4*)&hout[(size_t)m*128 + col] = hv;
        }
    }
}

// ---------------- attention: one block per (b,h), 512 threads, single pass ----------------
__global__ __launch_bounds__(512) void attnK(const float* __restrict__ qkv,
                                             const int* __restrict__ mask,
                                             float* __restrict__ out) {
    extern __shared__ float sm[];
    float* Ks = sm;             // 512*16
    float* Vs = sm + 8192;      // 512*16
    float* Ms = sm + 16384;     // 512
    int b = blockIdx.x >> 3, h = blockIdx.x & 7;
    int t = threadIdx.x;
    const float* q = qkv;
    const float* k = qkv + ELEMS;
    const float* v = qkv + 2*ELEMS;

    #pragma unroll
    for (int p = 0; p < 4; p++) {
        int i4 = p*512 + t;                  // 2048 float4 slots
        int tok = i4 >> 2, c4 = (i4 & 3) * 4;
        int g = (b*512 + tok)*128 + h*16 + c4;
        *(float4*)&Ks[tok*16 + c4] = *(const float4*)&k[g];
        *(float4*)&Vs[tok*16 + c4] = *(const float4*)&v[g];
    }
    Ms[t & 511] = mask[b*512 + (t & 511)] ? 0.f : -1e30f;
    __syncthreads();

    int s = t;
    float qr[16];
    #pragma unroll
    for (int c = 0; c < 16; c += 4)
        *(float4*)&qr[c] = *(const float4*)&q[(b*512 + s)*128 + h*16 + c];

    float l = 0.f;
    float o[16];
    #pragma unroll
    for (int c = 0; c < 16; c++) o[c] = 0.f;

    #pragma unroll 2
    for (int t2 = 0; t2 < 512; t2++) {
        const float* kr = &Ks[t2*16];
        float4 k0 = *(const float4*)&kr[0];
        float4 k1 = *(const float4*)&kr[4];
        float4 k2 = *(const float4*)&kr[8];
        float4 k3 = *(const float4*)&kr[12];
        float sc = qr[0]*k0.x + qr[1]*k0.y + qr[2]*k0.z + qr[3]*k0.w
                 + qr[4]*k1.x + qr[5]*k1.y + qr[6]*k1.z + qr[7]*k1.w
                 + qr[8]*k2.x + qr[9]*k2.y + qr[10]*k2.z + qr[11]*k2.w
                 + qr[12]*k3.x + qr[13]*k3.y + qr[14]*k3.z + qr[15]*k3.w;
        float p = __expf(sc*0.25f + Ms[t2]);
        l += p;
        const float* vr = &Vs[t2*16];
        float4 v0 = *(const float4*)&vr[0];
        float4 v1 = *(const float4*)&vr[4];
        float4 v2 = *(const float4*)&vr[8];
        float4 v3 = *(const float4*)&vr[12];
        o[0]+=p*v0.x; o[1]+=p*v0.y; o[2]+=p*v0.z; o[3]+=p*v0.w;
        o[4]+=p*v1.x; o[5]+=p*v1.y; o[6]+=p*v1.z; o[7]+=p*v1.w;
        o[8]+=p*v2.x; o[9]+=p*v2.y; o[10]+=p*v2.z; o[11]+=p*v2.w;
        o[12]+=p*v3.x; o[13]+=p*v3.y; o[14]+=p*v3.z; o[15]+=p*v3.w;
    }
    float inv = 1.f / l;
    __syncthreads();
    #pragma unroll
    for (int c = 0; c < 16; c += 4) {
        float4 ov = {o[c]*inv, o[c+1]*inv, o[c+2]*inv, o[c+3]*inv};
        *(float4*)&Ks[s*16 + c] = ov;
    }
    __syncthreads();
    #pragma unroll
    for (int p = 0; p < 4; p++) {
        int i4 = p*512 + t;
        int tok = i4 >> 2, c4 = (i4 & 3) * 4;
        *(float4*)&out[(b*512 + tok)*128 + h*16 + c4] = *(const float4*)&Ks[tok*16 + c4];
    }
}

// ---------------- launch ----------------
extern "C" void kernel_launch(void* const* d_in, const int* in_sizes, int n_in,
                              void* d_out, int out_size) {
    const float* x     = (const float*)d_in[0];
    const int*   mask  = (const int*)  d_in[1];
    const float* ln_s  = (const float*)d_in[2];
    const float* ln_b  = (const float*)d_in[3];
    const float* dw_w  = (const float*)d_in[4];
    const float* dw_b  = (const float*)d_in[5];
    const float* pw_w  = (const float*)d_in[6];
    const float* pw_b  = (const float*)d_in[7];
    const float* Wq    = (const float*)d_in[8];
    const float* Wk    = (const float*)d_in[9];
    const float* Wv    = (const float*)d_in[10];
    const float* Wo    = (const float*)d_in[11];
    const float* ab    = (const float*)d_in[12];
    const float* f1w   = (const float*)d_in[13];
    const float* f1b   = (const float*)d_in[14];
    const float* f2w   = (const float*)d_in[15];
    const float* f2b   = (const float*)d_in[16];
    float* out = (float*)d_out;

    float *hA, *hB, *aP, *qkvP, *wTP;
    cudaGetSymbolAddress((void**)&hA,   g_h);
    cudaGetSymbolAddress((void**)&hB,   g_h2);
    cudaGetSymbolAddress((void**)&aP,   g_a);
    cudaGetSymbolAddress((void**)&qkvP, g_qkv);
    cudaGetSymbolAddress((void**)&wTP,  g_wT);

    const int GSMEM = (64*128 + 128*128) * 4;       // 96 KB
    const int ASMEM = (8192 + 8192 + 512) * 4;      // 66 KB

    // conv layer i: DW + pw + bias + relu + res, epilogue LN[i+1]
    auto gConv = gemmF<true,  false, 1, true,  true,  true>;
    auto gQKV  = gemmF<false, true,  2, false, false, false>;
    auto gWo   = gemmF<false, false, 2, false, true,  true>;
    auto gF1   = gemmF<false, false, 1, true,  false, false>;
    auto gF2   = gemmF<false, false, 1, false, true,  false>;
    cudaFuncSetAttribute(gConv, cudaFuncAttributeMaxDynamicSharedMemorySize, GSMEM);
    cudaFuncSetAttribute(gQKV,  cudaFuncAttributeMaxDynamicSharedMemorySize, GSMEM);
    cudaFuncSetAttribute(gWo,   cudaFuncAttributeMaxDynamicSharedMemorySize, GSMEM);
    cudaFuncSetAttribute(gF1,   cudaFuncAttributeMaxDynamicSharedMemorySize, GSMEM);
    cudaFuncSetAttribute(gF2,   cudaFuncAttributeMaxDynamicSharedMemorySize, GSMEM);
    cudaFuncSetAttribute(attnK, cudaFuncAttributeMaxDynamicSharedMemorySize, ASMEM);

    prep_weights<<<576, 256>>>(Wq, Wk, Wv, pw_w, f1w, f2w, wTP);
    addpos_ln<<<128, 512>>>(x, out, hA, ln_s, ln_b);

    float* hin = hA; float* hob = hB;
    for (int i = 0; i < 4; i++) {
        gConv<<<128, 512, GSMEM>>>(hin, wTP + (3+i)*16384, pw_b + i*128, out, out, hob,
                                   ln_s + (i+1)*128, ln_b + (i+1)*128,
                                   dw_w + i*896, dw_b + i*128);
        float* tmp = hin; hin = hob; hob = tmp;
    }
    // hin now holds attention LN (ln[4])
    gQKV<<<dim3(128,3), 512, GSMEM>>>(hin, wTP, ab, nullptr, qkvP, nullptr,
                                      nullptr, nullptr, nullptr, nullptr);
    attnK<<<128, 512, ASMEM>>>(qkvP, mask, aP);
    gWo<<<128, 512, GSMEM>>>(aP, Wo, ab, out, out, hob,
                             ln_s + 5*128, ln_b + 5*128, nullptr, nullptr);
    gF1<<<128, 512, GSMEM>>>(hob, wTP + 7*16384, f1b, nullptr, aP, nullptr,
                             nullptr, nullptr, nullptr, nullptr);
    gF2<<<128, 512, GSMEM>>>(aP, wTP + 8*16384, f2b, out, out, nullptr,
                             nullptr, nullptr, nullptr, nullptr);
}

// round 5
// speedup vs baseline: 1.8268x; 1.0477x over previous
#include <cuda_runtime.h>
#include <math.h>

#define TOKS 8192
#define ELEMS 1048576
typedef unsigned long long ull;

// ---------------- scratch ----------------
__device__ float g_h[ELEMS];
__device__ float g_h2[ELEMS];
__device__ float g_a[ELEMS];
__device__ float g_qkv[3*ELEMS];
__device__ float g_wT[9*16384];   // [0..2] qkv, [3..6] pw, [7] f1, [8] f2  (all [K][N])

// ---------------- f32x2 helpers ----------------
__device__ __forceinline__ ull ffma2(ull a, ull b, ull c) {
    ull d;
    asm("fma.rn.f32x2 %0, %1, %2, %3;" : "=l"(d) : "l"(a), "l"(b), "l"(c));
    return d;
}
__device__ __forceinline__ ull add2(ull a, ull b) {
    ull d;
    asm("add.rn.f32x2 %0, %1, %2;" : "=l"(d) : "l"(a), "l"(b));
    return d;
}
__device__ __forceinline__ ull pack2(float a, float b) {
    ull d;
    asm("mov.b64 %0, {%1, %2};" : "=l"(d) : "f"(a), "f"(b));
    return d;
}
__device__ __forceinline__ void unpack2(ull v, float& lo, float& hi) {
    asm("mov.b64 {%0, %1}, %2;" : "=f"(lo), "=f"(hi) : "l"(v));
}
__device__ __forceinline__ float ex2f(float x) {
    float r;
    asm("ex2.approx.f32 %0, %1;" : "=f"(r) : "f"(x));
    return r;
}

// ---------------- weight prep: repack/transpose to [K=128][N=128] ----------------
__global__ void prep_weights(const float* __restrict__ Wq, const float* __restrict__ Wk,
                             const float* __restrict__ Wv, const float* __restrict__ pw,
                             const float* __restrict__ f1, const float* __restrict__ f2,
                             float* __restrict__ wT) {
    int idx = blockIdx.x*256 + threadIdx.x;          // 9*16384
    if (idx >= 9*16384) return;
    int j = idx >> 14, r = idx & 16383;
    int d = r >> 7, n = r & 127;
    float v;
    if (j < 3) {
        const float* W = (j==0) ? Wq : (j==1) ? Wk : Wv;   // (H,128,16)
        v = W[(n>>4)*2048 + d*16 + (n&15)];
    } else if (j < 7) {
        v = pw[(j-3)*16384 + n*128 + d];                    // (D_out, D_in) -> [in][out]
    } else {
        const float* W = (j==7) ? f1 : f2;
        v = W[n*128 + d];                                    // f_w.T
    }
    wT[idx] = v;
}

// ---------------- addpos + LN0 : out = x+pos, h = LN(out) ----------------
__global__ __launch_bounds__(512) void addpos_ln(const float* __restrict__ x,
                                                 float* __restrict__ out, float* __restrict__ hout,
                                                 const float* __restrict__ lnS,
                                                 const float* __restrict__ lnB) {
    int m0 = blockIdx.x * 64;
    int lane = threadIdx.x & 31, warp = threadIdx.x >> 5;
    int col = lane * 4;
    const float inc = 0.14619588050756158f;   // log(10000)/63
    float4 g4 = *(const float4*)&lnS[col];
    float4 b4 = *(const float4*)&lnB[col];
    #pragma unroll
    for (int i = 0; i < 4; i++) {
        int m = m0 + warp*4 + i;
        int s = m & 511;
        float4 xv = *(const float4*)&x[m*128 + col];
        float v[4] = {xv.x, xv.y, xv.z, xv.w};
        #pragma unroll
        for (int jj = 0; jj < 4; jj++) {
            int d = col + jj;
            int dd = d & 63;
            float a = (float)s * expf(-inc*(float)dd);
            v[jj] += (d < 64) ? sinf(a) : cosf(a);
        }
        float rs_ = v[0]+v[1]+v[2]+v[3];
        float rq  = v[0]*v[0]+v[1]*v[1]+v[2]*v[2]+v[3]*v[3];
        #pragma unroll
        for (int o = 16; o > 0; o >>= 1) {
            rs_ += __shfl_xor_sync(0xffffffffu, rs_, o);
            rq  += __shfl_xor_sync(0xffffffffu, rq,  o);
        }
        float mu  = rs_ * (1.0f/128.0f);
        float var = rq  * (1.0f/128.0f) - mu*mu;
        float rinv = rsqrtf(var + 1e-5f);
        float4 ov = {v[0], v[1], v[2], v[3]};
        *(float4*)&out[m*128 + col] = ov;
        float4 hv;
        hv.x = (v[0]-mu)*rinv*g4.x + b4.x;
        hv.y = (v[1]-mu)*rinv*g4.y + b4.y;
        hv.z = (v[2]-mu)*rinv*g4.z + b4.z;
        hv.w = (v[3]-mu)*rinv*g4.w + b4.w;
        *(float4*)&hout[m*128 + col] = hv;
    }
}

// ---------------- fused GEMM: [64xM tile] x [128K x 128N], 512 threads ----------------
template<bool DW, bool MULTI, int BIASM, bool RELU, bool RES, bool LN>
__global__ __launch_bounds__(512) void gemmF(
    const float* __restrict__ A, const float* __restrict__ W,
    const float* __restrict__ bias, const float* __restrict__ res,
    float* __restrict__ out, float* __restrict__ hout,
    const float* __restrict__ lnS, const float* __restrict__ lnB,
    const float* __restrict__ dww, const float* __restrict__ dwb)
{
    extern __shared__ float sm[];
    float (*As)[128] = (float(*)[128])sm;            // 64 x 128 (m-major)
    float (*Ws)[128] = (float(*)[128])(sm + 64*128); // 128 x 128 (k-major)
    if (MULTI) { W += blockIdx.y * 16384; out += (size_t)blockIdx.y * ELEMS; }

    int m0 = blockIdx.x * 64;
    int t = threadIdx.x;
    int lane = t & 31, warp = t >> 5;

    // load W (k = warp*8+p, n4 = lane*4): coalesced, conflict-free
    #pragma unroll
    for (int p = 0; p < 8; p++) {
        int k = warp*8 + p;
        *(float4*)&Ws[k][lane*4] = *(const float4*)&W[k*128 + lane*4];
    }

    if (DW) {
        int d = t & 127, q = t >> 7;
        float wr[7];
        #pragma unroll
        for (int kk = 0; kk < 7; kk++) wr[kk] = dww[d*7 + kk];
        float db = dwb[d];
        int sBase = (m0 & 511) + q*16;
        const float* hb = A + (size_t)(m0 & ~511) * 128;
        float hwin[22];
        #pragma unroll
        for (int jj = 0; jj < 22; jj++) {
            int s = sBase + jj - 3;
            hwin[jj] = (s >= 0 && s < 512) ? hb[s*128 + d] : 0.f;
        }
        #pragma unroll
        for (int i = 0; i < 16; i++) {
            float acc = db;
            #pragma unroll
            for (int kk = 0; kk < 7; kk++) acc += wr[kk] * hwin[i+kk];
            As[q*16 + i][d] = acc;
        }
    } else {
        #pragma unroll
        for (int p = 0; p < 4; p++) {
            int m = warp*4 + p;
            *(float4*)&As[m][lane*4] = *(const float4*)&A[(size_t)(m0+m)*128 + lane*4];
        }
    }
    __syncthreads();

    // f32x2 main loop: acc pairs over adjacent columns
    ull acc01[4] = {0,0,0,0};
    ull acc23[4] = {0,0,0,0};
    int row0 = warp*4, col = lane*4;
    #pragma unroll 4
    for (int k = 0; k < 128; k += 4) {
        float4 af[4];
        #pragma unroll
        for (int i = 0; i < 4; i++) af[i] = *(const float4*)&As[row0+i][k];
        #pragma unroll
        for (int kk = 0; kk < 4; kk++) {
            ulonglong2 b2 = *(const ulonglong2*)&Ws[k+kk][col];
            #pragma unroll
            for (int i = 0; i < 4; i++) {
                float a = (kk==0) ? af[i].x : (kk==1) ? af[i].y : (kk==2) ? af[i].z : af[i].w;
                ull aa = pack2(a, a);
                acc01[i] = ffma2(aa, b2.x, acc01[i]);
                acc23[i] = ffma2(aa, b2.y, acc23[i]);
            }
        }
    }

    // epilogue
    float4 bv = {0,0,0,0};
    if (BIASM == 1) bv = *(const float4*)&bias[col];
    float bs = (BIASM == 2) ? bias[0] : 0.f;
    float4 g4 = {0,0,0,0}, lb4 = {0,0,0,0};
    if (LN) { g4 = *(const float4*)&lnS[col]; lb4 = *(const float4*)&lnB[col]; }

    #pragma unroll
    for (int i = 0; i < 4; i++) {
        int m = m0 + row0 + i;
        float v[4];
        unpack2(acc01[i], v[0], v[1]);
        unpack2(acc23[i], v[2], v[3]);
        #pragma unroll
        for (int jj = 0; jj < 4; jj++) {
            float val = v[jj];
            if (BIASM == 1) val += ((const float*)&bv)[jj];
            if (BIASM == 2) val += bs;
            if (RELU) val = fmaxf(val, 0.f);
            v[jj] = val;
        }
        if (RES) {
            float4 r4 = *(const float4*)&res[(size_t)m*128 + col];
            v[0] += r4.x; v[1] += r4.y; v[2] += r4.z; v[3] += r4.w;
        }
        float4 ov = {v[0], v[1], v[2], v[3]};
        *(float4*)&out[(size_t)m*128 + col] = ov;
        if (LN) {
            float rs_ = v[0]+v[1]+v[2]+v[3];
            float rq  = v[0]*v[0]+v[1]*v[1]+v[2]*v[2]+v[3]*v[3];
            #pragma unroll
            for (int o = 16; o > 0; o >>= 1) {
                rs_ += __shfl_xor_sync(0xffffffffu, rs_, o);
                rq  += __shfl_xor_sync(0xffffffffu, rq,  o);
            }
            float mu  = rs_ * (1.0f/128.0f);
            float var = rq  * (1.0f/128.0f) - mu*mu;
            float rinv = rsqrtf(var + 1e-5f);
            float4 hv;
            hv.x = (v[0]-mu)*rinv*g4.x + lb4.x;
            hv.y = (v[1]-mu)*rinv*g4.y + lb4.y;
            hv.z = (v[2]-mu)*rinv*g4.z + lb4.z;
            hv.w = (v[3]-mu)*rinv*g4.w + lb4.w;
            *(float4*)&hout[(size_t)m*128 + col] = hv;
        }
    }
}

// ---------------- attention: one block per (b,h), 512 threads, f32x2, exp2 domain ----------------
__global__ __launch_bounds__(512) void attnK(const float* __restrict__ qkv,
                                             const int* __restrict__ mask,
                                             float* __restrict__ out) {
    extern __shared__ float sm[];
    float* Ks = sm;             // 512*16
    float* Vs = sm + 8192;      // 512*16
    float* Ms = sm + 16384;     // 512
    int b = blockIdx.x >> 3, h = blockIdx.x & 7;
    int t = threadIdx.x;
    const float* q = qkv;
    const float* k = qkv + ELEMS;
    const float* v = qkv + 2*ELEMS;

    #pragma unroll
    for (int p = 0; p < 4; p++) {
        int i4 = p*512 + t;                  // 2048 float4 slots
        int tok = i4 >> 2, c4 = (i4 & 3) * 4;
        int g = (b*512 + tok)*128 + h*16 + c4;
        *(float4*)&Ks[tok*16 + c4] = *(const float4*)&k[g];
        *(float4*)&Vs[tok*16 + c4] = *(const float4*)&v[g];
    }
    Ms[t & 511] = mask[b*512 + (t & 511)] ? 0.f : -1e30f;
    __syncthreads();

    int s = t;
    // load q, pre-scale by 0.25 * log2(e)
    const float qsc = 0.25f * 1.4426950408889634f;
    ull qsp = pack2(qsc, qsc);
    ull qp[8];
    #pragma unroll
    for (int c = 0; c < 4; c++) {
        ulonglong2 q2 = *(const ulonglong2*)&q[(b*512 + s)*128 + h*16 + c*4];
        ull zero = 0;
        qp[c*2]   = ffma2(q2.x, qsp, zero);
        qp[c*2+1] = ffma2(q2.y, qsp, zero);
    }

    float l = 0.f;
    ull o[8] = {0,0,0,0,0,0,0,0};

    #pragma unroll 2
    for (int t2 = 0; t2 < 512; t2++) {
        const float* kr = &Ks[t2*16];
        ulonglong2 ka = *(const ulonglong2*)&kr[0];
        ulonglong2 kb = *(const ulonglong2*)&kr[4];
        ulonglong2 kc = *(const ulonglong2*)&kr[8];
        ulonglong2 kd = *(const ulonglong2*)&kr[12];
        ull za = 0, zb = 0;
        za = ffma2(qp[0], ka.x, za);
        za = ffma2(qp[1], ka.y, za);
        za = ffma2(qp[2], kb.x, za);
        za = ffma2(qp[3], kb.y, za);
        zb = ffma2(qp[4], kc.x, zb);
        zb = ffma2(qp[5], kc.y, zb);
        zb = ffma2(qp[6], kd.x, zb);
        zb = ffma2(qp[7], kd.y, zb);
        ull zc = add2(za, zb);
        float lo, hi;
        unpack2(zc, lo, hi);
        float sc = lo + hi + Ms[t2];
        float p = ex2f(sc);          // = exp(0.25*q.k) for valid, 0 for masked
        l += p;
        ull pp = pack2(p, p);
        const float* vr = &Vs[t2*16];
        ulonglong2 va = *(const ulonglong2*)&vr[0];
        ulonglong2 vb = *(const ulonglong2*)&vr[4];
        ulonglong2 vc = *(const ulonglong2*)&vr[8];
        ulonglong2 vd = *(const ulonglong2*)&vr[12];
        o[0] = ffma2(pp, va.x, o[0]);
        o[1] = ffma2(pp, va.y, o[1]);
        o[2] = ffma2(pp, vb.x, o[2]);
        o[3] = ffma2(pp, vb.y, o[3]);
        o[4] = ffma2(pp, vc.x, o[4]);
        o[5] = ffma2(pp, vc.y, o[5]);
        o[6] = ffma2(pp, vd.x, o[6]);
        o[7] = ffma2(pp, vd.y, o[7]);
    }
    float inv = 1.f / l;
    float of[16];
    #pragma unroll
    for (int c = 0; c < 8; c++) {
        unpack2(o[c], of[c*2], of[c*2+1]);
        of[c*2]   *= inv;
        of[c*2+1] *= inv;
    }
    __syncthreads();
    #pragma unroll
    for (int c = 0; c < 16; c += 4) {
        float4 ov = {of[c], of[c+1], of[c+2], of[c+3]};
        *(float4*)&Ks[s*16 + c] = ov;
    }
    __syncthreads();
    #pragma unroll
    for (int p = 0; p < 4; p++) {
        int i4 = p*512 + t;
        int tok = i4 >> 2, c4 = (i4 & 3) * 4;
        *(float4*)&out[(b*512 + tok)*128 + h*16 + c4] = *(const float4*)&Ks[tok*16 + c4];
    }
}

// ---------------- launch ----------------
extern "C" void kernel_launch(void* const* d_in, const int* in_sizes, int n_in,
                              void* d_out, int out_size) {
    const float* x     = (const float*)d_in[0];
    const int*   mask  = (const int*)  d_in[1];
    const float* ln_s  = (const float*)d_in[2];
    const float* ln_b  = (const float*)d_in[3];
    const float* dw_w  = (const float*)d_in[4];
    const float* dw_b  = (const float*)d_in[5];
    const float* pw_w  = (const float*)d_in[6];
    const float* pw_b  = (const float*)d_in[7];
    const float* Wq    = (const float*)d_in[8];
    const float* Wk    = (const float*)d_in[9];
    const float* Wv    = (const float*)d_in[10];
    const float* Wo    = (const float*)d_in[11];
    const float* ab    = (const float*)d_in[12];
    const float* f1w   = (const float*)d_in[13];
    const float* f1b   = (const float*)d_in[14];
    const float* f2w   = (const float*)d_in[15];
    const float* f2b   = (const float*)d_in[16];
    float* out = (float*)d_out;

    float *hA, *hB, *aP, *qkvP, *wTP;
    cudaGetSymbolAddress((void**)&hA,   g_h);
    cudaGetSymbolAddress((void**)&hB,   g_h2);
    cudaGetSymbolAddress((void**)&aP,   g_a);
    cudaGetSymbolAddress((void**)&qkvP, g_qkv);
    cudaGetSymbolAddress((void**)&wTP,  g_wT);

    const int GSMEM = (64*128 + 128*128) * 4;       // 96 KB
    const int ASMEM = (8192 + 8192 + 512) * 4;      // 66 KB

    auto gConv = gemmF<true,  false, 1, true,  true,  true>;
    auto gQKV  = gemmF<false, true,  2, false, false, false>;
    auto gWo   = gemmF<false, false, 2, false, true,  true>;
    auto gF1   = gemmF<false, false, 1, true,  false, false>;
    auto gF2   = gemmF<false, false, 1, false, true,  false>;
    cudaFuncSetAttribute(gConv, cudaFuncAttributeMaxDynamicSharedMemorySize, GSMEM);
    cudaFuncSetAttribute(gQKV,  cudaFuncAttributeMaxDynamicSharedMemorySize, GSMEM);
    cudaFuncSetAttribute(gWo,   cudaFuncAttributeMaxDynamicSharedMemorySize, GSMEM);
    cudaFuncSetAttribute(gF1,   cudaFuncAttributeMaxDynamicSharedMemorySize, GSMEM);
    cudaFuncSetAttribute(gF2,   cudaFuncAttributeMaxDynamicSharedMemorySize, GSMEM);
    cudaFuncSetAttribute(attnK, cudaFuncAttributeMaxDynamicSharedMemorySize, ASMEM);

    prep_weights<<<576, 256>>>(Wq, Wk, Wv, pw_w, f1w, f2w, wTP);
    addpos_ln<<<128, 512>>>(x, out, hA, ln_s, ln_b);

    float* hin = hA; float* hob = hB;
    for (int i = 0; i < 4; i++) {
        gConv<<<128, 512, GSMEM>>>(hin, wTP + (3+i)*16384, pw_b + i*128, out, out, hob,
                                   ln_s + (i+1)*128, ln_b + (i+1)*128,
                                   dw_w + i*896, dw_b + i*128);
        float* tmp = hin; hin = hob; hob = tmp;
    }
    // hin now holds attention LN (ln[4])
    gQKV<<<dim3(128,3), 512, GSMEM>>>(hin, wTP, ab, nullptr, qkvP, nullptr,
                                      nullptr, nullptr, nullptr, nullptr);
    attnK<<<128, 512, ASMEM>>>(qkvP, mask, aP);
    gWo<<<128, 512, GSMEM>>>(aP, Wo, ab, out, out, hob,
                             ln_s + 5*128, ln_b + 5*128, nullptr, nullptr);
    gF1<<<128, 512, GSMEM>>>(hob, wTP + 7*16384, f1b, nullptr, aP, nullptr,
                             nullptr, nullptr, nullptr, nullptr);
    gF2<<<128, 512, GSMEM>>>(aP, wTP + 8*16384, f2b, out, out, nullptr,
                             nullptr, nullptr, nullptr, nullptr);
}

// round 6
// speedup vs baseline: 2.2293x; 1.2203x over previous
#include <cuda_runtime.h>
#include <cuda_bf16.h>
#include <math.h>

#define TOKS 8192
#define ELEMS 1048576
typedef unsigned long long ull;
typedef unsigned int u32;
typedef unsigned short u16;

// ---------------- scratch ----------------
__device__ float g_h[ELEMS];
__device__ float g_h2[ELEMS];
__device__ float g_a[ELEMS];
__device__ float g_qkv[3*ELEMS];
// 10 weight matrices in mma-fragment order, hi/lo bf16 split:
// per matrix: u32[2 parts][8 kt][16 nt][32 lane][2 reg] = 16384 u32
__device__ u32 g_wB[10*16384];

// ---------------- helpers ----------------
__device__ __forceinline__ u16 bfhi(float v) {
    return __bfloat16_as_ushort(__float2bfloat16_rn(v));
}
__device__ __forceinline__ float bf2f(u16 u) {
    return __bfloat162float(__ushort_as_bfloat16(u));
}
__device__ __forceinline__ float ex2f(float x) {
    float r; asm("ex2.approx.f32 %0, %1;" : "=f"(r) : "f"(x)); return r;
}
__device__ __forceinline__ ull ffma2(ull a, ull b, ull c) {
    ull d; asm("fma.rn.f32x2 %0, %1, %2, %3;" : "=l"(d) : "l"(a), "l"(b), "l"(c)); return d;
}
__device__ __forceinline__ ull add2(ull a, ull b) {
    ull d; asm("add.rn.f32x2 %0, %1, %2;" : "=l"(d) : "l"(a), "l"(b)); return d;
}
__device__ __forceinline__ ull pack2(float a, float b) {
    ull d; asm("mov.b64 %0, {%1, %2};" : "=l"(d) : "f"(a), "f"(b)); return d;
}
__device__ __forceinline__ void unpack2(ull v, float& lo, float& hi) {
    asm("mov.b64 {%0, %1}, %2;" : "=f"(lo), "=f"(hi) : "l"(v));
}
__device__ __forceinline__ void mma16816(float4& c, const uint4& a, const uint2& b) {
    asm("mma.sync.aligned.m16n8k16.row.col.f32.bf16.bf16.f32 "
        "{%0,%1,%2,%3}, {%4,%5,%6,%7}, {%8,%9}, {%0,%1,%2,%3};"
        : "+f"(c.x), "+f"(c.y), "+f"(c.z), "+f"(c.w)
        : "r"(a.x), "r"(a.y), "r"(a.z), "r"(a.w), "r"(b.x), "r"(b.y));
}

// ---------------- weight prep: split + pack to B-fragment order ----------------
// matrices: 0..2 qkv, 3..6 pw, 7 f1, 8 f2, 9 Wo.  W[k][n] logical.
__global__ void prep_weights(const float* __restrict__ Wq, const float* __restrict__ Wk,
                             const float* __restrict__ Wv, const float* __restrict__ pw,
                             const float* __restrict__ f1, const float* __restrict__ f2,
                             const float* __restrict__ Wo, u32* __restrict__ wB) {
    int idx = blockIdx.x*256 + threadIdx.x;          // 10*16384
    if (idx >= 10*16384) return;
    int j = idx >> 14, r = idx & 16383;
    int k = r >> 7, n = r & 127;
    float v;
    if (j < 3) {
        const float* W = (j==0) ? Wq : (j==1) ? Wk : Wv;   // (H,128,16)
        v = W[(n>>4)*2048 + k*16 + (n&15)];
    } else if (j < 7) {
        v = pw[(j-3)*16384 + n*128 + k];                    // (out,in) -> [k][n]
    } else if (j < 9) {
        const float* W = (j==7) ? f1 : f2;
        v = W[n*128 + k];                                    // f_w.T
    } else {
        v = Wo[k*128 + n];
    }
    u16 h = bfhi(v);
    u16 l = bfhi(v - bf2f(h));
    // B frag coords
    int kt = k >> 4, kk = k & 15;
    int reg = kk >> 3, tig = (kk & 7) >> 1, bb = kk & 1;
    int nt = n >> 3, lane = (n & 7)*4 + tig;
    u16* w16 = (u16*)(wB + (size_t)j*16384);
    int i32h = ((kt*16 + nt)*32 + lane)*2 + reg;            // p=0
    int i32l = (((8 + kt)*16 + nt)*32 + lane)*2 + reg;      // p=1
    w16[i32h*2 + bb] = h;
    w16[i32l*2 + bb] = l;
}

// ---------------- addpos + LN0 ----------------
__global__ __launch_bounds__(512) void addpos_ln(const float* __restrict__ x,
                                                 float* __restrict__ out, float* __restrict__ hout,
                                                 const float* __restrict__ lnS,
                                                 const float* __restrict__ lnB) {
    int m0 = blockIdx.x * 64;
    int lane = threadIdx.x & 31, warp = threadIdx.x >> 5;
    int col = lane * 4;
    const float inc = 0.14619588050756158f;   // log(10000)/63
    float4 g4 = *(const float4*)&lnS[col];
    float4 b4 = *(const float4*)&lnB[col];
    #pragma unroll
    for (int i = 0; i < 4; i++) {
        int m = m0 + warp*4 + i;
        int s = m & 511;
        float4 xv = *(const float4*)&x[m*128 + col];
        float v[4] = {xv.x, xv.y, xv.z, xv.w};
        #pragma unroll
        for (int jj = 0; jj < 4; jj++) {
            int d = col + jj;
            int dd = d & 63;
            float a = (float)s * expf(-inc*(float)dd);
            v[jj] += (d < 64) ? sinf(a) : cosf(a);
        }
        float rs_ = v[0]+v[1]+v[2]+v[3];
        float rq  = v[0]*v[0]+v[1]*v[1]+v[2]*v[2]+v[3]*v[3];
        #pragma unroll
        for (int o = 16; o > 0; o >>= 1) {
            rs_ += __shfl_xor_sync(0xffffffffu, rs_, o);
            rq  += __shfl_xor_sync(0xffffffffu, rq,  o);
        }
        float mu  = rs_ * (1.0f/128.0f);
        float var = rq  * (1.0f/128.0f) - mu*mu;
        float rinv = rsqrtf(var + 1e-5f);
        float4 ov = {v[0], v[1], v[2], v[3]};
        *(float4*)&out[m*128 + col] = ov;
        float4 hv;
        hv.x = (v[0]-mu)*rinv*g4.x + b4.x;
        hv.y = (v[1]-mu)*rinv*g4.y + b4.y;
        hv.z = (v[2]-mu)*rinv*g4.z + b4.z;
        hv.w = (v[3]-mu)*rinv*g4.w + b4.w;
        *(float4*)&hout[m*128 + col] = hv;
    }
}

// ---------------- tensor-core GEMM: 64xM tile, full K=128, N=128, 256 thr ----------------
// smem u32 layout: B32[16384] | A32[8192] (C f32[64][132] aliases A region)
template<bool DW, bool MULTI, int BIASM, bool RELU, bool RES, bool LN>
__global__ __launch_bounds__(256) void gemmT(
    const float* __restrict__ A, const u32* __restrict__ Wf,
    const float* __restrict__ bias, const float* __restrict__ res,
    float* __restrict__ out, float* __restrict__ hout,
    const float* __restrict__ lnS, const float* __restrict__ lnB,
    const float* __restrict__ dww, const float* __restrict__ dwb)
{
    extern __shared__ u32 smu[];
    u32* B32 = smu;                   // 16384 u32
    u32* A32 = smu + 16384;           // 8192 u32
    float* Csm = (float*)(smu + 16384); // 64 x 132 f32
    if (MULTI) { Wf += blockIdx.y * 16384; out += (size_t)blockIdx.y * ELEMS; }

    int m0 = blockIdx.x * 64;
    int t = threadIdx.x, lane = t & 31, warp = t >> 5;

    // stage B fragments (already frag-ordered in gmem)
    #pragma unroll
    for (int i = 0; i < 16; i++)
        *(uint4*)&B32[i*1024 + t*4] = *(const uint4*)&Wf[i*1024 + t*4];

    u16* A16 = (u16*)A32;
    if (DW) {
        // depthwise conv7 producer: thread owns channel d, 32 tokens
        int d = t & 127, q = t >> 7;
        float wr[7];
        #pragma unroll
        for (int kk = 0; kk < 7; kk++) wr[kk] = dww[d*7 + kk];
        float db = dwb[d];
        int kt = d >> 4;
        int tig = (d & 7) >> 1, bb = d & 1;
        int kreg2 = ((d & 15) >> 3) * 2;
        const float* hb = A + (size_t)(m0 & ~511) * 128;
        int sBase = (m0 & 511) + q*32;
        #pragma unroll
        for (int half = 0; half < 2; half++) {
            float hwin[22];
            #pragma unroll
            for (int jj = 0; jj < 22; jj++) {
                int s = sBase + half*16 + jj - 3;
                hwin[jj] = (s >= 0 && s < 512) ? hb[s*128 + d] : 0.f;
            }
            #pragma unroll
            for (int i = 0; i < 16; i++) {
                float acc = db;
                #pragma unroll
                for (int kk = 0; kk < 7; kk++) acc += wr[kk] * hwin[i+kk];
                int ml = q*32 + half*16 + i;
                int mt = ml >> 4, mm = ml & 15;
                int g = mm & 7, hi8 = mm >> 3;
                int reg = hi8 + kreg2;
                int ln2 = g*4 + tig;
                u16 h = bfhi(acc);
                u16 l = bfhi(acc - bf2f(h));
                int ih = ((mt*8 + kt)*32 + ln2)*4 + reg;
                int il = (((4 + mt)*8 + kt)*32 + ln2)*4 + reg;
                A16[ih*2 + bb] = h;
                A16[il*2 + bb] = l;
            }
        }
    } else {
        #pragma unroll
        for (int i = 0; i < 8; i++) {
            int idx4 = i*256 + t;
            int m = idx4 >> 5;
            int k0 = (idx4 & 31) * 4;
            float4 v = *(const float4*)&A[(size_t)(m0 + m)*128 + k0];
            float vv[4] = {v.x, v.y, v.z, v.w};
            int mt = m >> 4, mm = m & 15;
            int g = mm & 7, hi8 = mm >> 3;
            int kt = k0 >> 4;
            #pragma unroll
            for (int j = 0; j < 4; j += 2) {
                int k = k0 + j;
                int tig = (k & 7) >> 1;
                int reg = hi8 + 2*((k & 15) >> 3);
                int ln2 = g*4 + tig;
                u16 h0 = bfhi(vv[j]),   l0 = bfhi(vv[j]   - bf2f(h0));
                u16 h1 = bfhi(vv[j+1]), l1 = bfhi(vv[j+1] - bf2f(h1));
                A32[((mt*8 + kt)*32 + ln2)*4 + reg]       = (u32)h0 | ((u32)h1 << 16);
                A32[(((4+mt)*8 + kt)*32 + ln2)*4 + reg]   = (u32)l0 | ((u32)l1 << 16);
            }
        }
    }
    __syncthreads();

    // mainloop: warp = (wm, wn): 2 m-tiles x 4 n-tiles, 3-term split mma
    int wm = warp >> 2, wn = warp & 3;
    int mt0 = wm*2, nt0 = wn*4;
    float4 acc[2][4];
    #pragma unroll
    for (int i = 0; i < 2; i++)
        #pragma unroll
        for (int j = 0; j < 4; j++) acc[i][j] = make_float4(0.f,0.f,0.f,0.f);

    #pragma unroll
    for (int kt = 0; kt < 8; kt++) {
        uint4 ah[2], al[2];
        #pragma unroll
        for (int i = 0; i < 2; i++) {
            ah[i] = *(const uint4*)&A32[(((mt0+i)*8 + kt)*32 + lane)*4];
            al[i] = *(const uint4*)&A32[(((4+mt0+i)*8 + kt)*32 + lane)*4];
        }
        uint2 bh[4], bl[4];
        #pragma unroll
        for (int j = 0; j < 4; j++) {
            bh[j] = *(const uint2*)&B32[((kt*16 + nt0+j)*32 + lane)*2];
            bl[j] = *(const uint2*)&B32[(((8+kt)*16 + nt0+j)*32 + lane)*2];
        }
        #pragma unroll
        for (int i = 0; i < 2; i++)
            #pragma unroll
            for (int j = 0; j < 4; j++) {
                mma16816(acc[i][j], ah[i], bh[j]);
                mma16816(acc[i][j], ah[i], bl[j]);
                mma16816(acc[i][j], al[i], bh[j]);
            }
    }
    __syncthreads();

    // scatter C to smem (padded rows: stride 132)
    #pragma unroll
    for (int i = 0; i < 2; i++)
        #pragma unroll
        for (int j = 0; j < 4; j++) {
            int row = (mt0+i)*16 + (lane >> 2);
            int col = (nt0+j)*8 + (lane & 3)*2;
            float2 lo = {acc[i][j].x, acc[i][j].y};
            float2 hi = {acc[i][j].z, acc[i][j].w};
            *(float2*)&Csm[row*132 + col]     = lo;
            *(float2*)&Csm[(row+8)*132 + col] = hi;
        }
    __syncthreads();

    // epilogue: warp handles 8 rows
    int colE = lane*4;
    float4 bv = {0,0,0,0};
    if (BIASM == 1) bv = *(const float4*)&bias[colE];
    float bs = (BIASM == 2) ? bias[0] : 0.f;
    float4 g4 = {0,0,0,0}, lb4 = {0,0,0,0};
    if (LN) { g4 = *(const float4*)&lnS[colE]; lb4 = *(const float4*)&lnB[colE]; }

    #pragma unroll
    for (int i = 0; i < 8; i++) {
        int row = warp*8 + i;
        int m = m0 + row;
        float4 c4 = *(const float4*)&Csm[row*132 + colE];
        float v[4] = {c4.x, c4.y, c4.z, c4.w};
        #pragma unroll
        for (int jj = 0; jj < 4; jj++) {
            float val = v[jj];
            if (BIASM == 1) val += ((const float*)&bv)[jj];
            if (BIASM == 2) val += bs;
            if (RELU) val = fmaxf(val, 0.f);
            v[jj] = val;
        }
        if (RES) {
            float4 r4 = *(const float4*)&res[(size_t)m*128 + colE];
            v[0] += r4.x; v[1] += r4.y; v[2] += r4.z; v[3] += r4.w;
        }
        float4 ov = {v[0], v[1], v[2], v[3]};
        *(float4*)&out[(size_t)m*128 + colE] = ov;
        if (LN) {
            float rs_ = v[0]+v[1]+v[2]+v[3];
            float rq  = v[0]*v[0]+v[1]*v[1]+v[2]*v[2]+v[3]*v[3];
            #pragma unroll
            for (int o = 16; o > 0; o >>= 1) {
                rs_ += __shfl_xor_sync(0xffffffffu, rs_, o);
                rq  += __shfl_xor_sync(0xffffffffu, rq,  o);
            }
            float mu  = rs_ * (1.0f/128.0f);
            float var = rq  * (1.0f/128.0f) - mu*mu;
            float rinv = rsqrtf(var + 1e-5f);
            float4 hv;
            hv.x = (v[0]-mu)*rinv*g4.x + lb4.x;
            hv.y = (v[1]-mu)*rinv*g4.y + lb4.y;
            hv.z = (v[2]-mu)*rinv*g4.z + lb4.z;
            hv.w = (v[3]-mu)*rinv*g4.w + lb4.w;
            *(float4*)&hout[(size_t)m*128 + colE] = hv;
        }
    }
}

// ---------------- attention: one block per (b,h), 512 threads, f32x2 + exp2 ----------------
__global__ __launch_bounds__(512) void attnK(const float* __restrict__ qkv,
                                             const int* __restrict__ mask,
                                             float* __restrict__ out) {
    extern __shared__ float sm[];
    float* Ks = sm;             // 512*16
    float* Vs = sm + 8192;      // 512*16
    float* Ms = sm + 16384;     // 512
    int b = blockIdx.x >> 3, h = blockIdx.x & 7;
    int t = threadIdx.x;
    const float* q = qkv;
    const float* k = qkv + ELEMS;
    const float* v = qkv + 2*ELEMS;

    #pragma unroll
    for (int p = 0; p < 4; p++) {
        int i4 = p*512 + t;
        int tok = i4 >> 2, c4 = (i4 & 3) * 4;
        int g = (b*512 + tok)*128 + h*16 + c4;
        *(float4*)&Ks[tok*16 + c4] = *(const float4*)&k[g];
        *(float4*)&Vs[tok*16 + c4] = *(const float4*)&v[g];
    }
    Ms[t & 511] = mask[b*512 + (t & 511)] ? 0.f : -1e30f;
    __syncthreads();

    int s = t;
    const float qsc = 0.25f * 1.4426950408889634f;
    ull qsp = pack2(qsc, qsc);
    ull qp[8];
    #pragma unroll
    for (int c = 0; c < 4; c++) {
        ulonglong2 q2 = *(const ulonglong2*)&q[(b*512 + s)*128 + h*16 + c*4];
        ull zero = 0;
        qp[c*2]   = ffma2(q2.x, qsp, zero);
        qp[c*2+1] = ffma2(q2.y, qsp, zero);
    }

    float l = 0.f;
    ull o[8] = {0,0,0,0,0,0,0,0};

    #pragma unroll 2
    for (int t2 = 0; t2 < 512; t2++) {
        const float* kr = &Ks[t2*16];
        ulonglong2 ka = *(const ulonglong2*)&kr[0];
        ulonglong2 kb = *(const ulonglong2*)&kr[4];
        ulonglong2 kc = *(const ulonglong2*)&kr[8];
        ulonglong2 kd = *(const ulonglong2*)&kr[12];
        ull za = 0, zb = 0;
        za = ffma2(qp[0], ka.x, za);
        za = ffma2(qp[1], ka.y, za);
        za = ffma2(qp[2], kb.x, za);
        za = ffma2(qp[3], kb.y, za);
        zb = ffma2(qp[4], kc.x, zb);
        zb = ffma2(qp[5], kc.y, zb);
        zb = ffma2(qp[6], kd.x, zb);
        zb = ffma2(qp[7], kd.y, zb);
        ull zc = add2(za, zb);
        float lo, hi;
        unpack2(zc, lo, hi);
        float sc = lo + hi + Ms[t2];
        float p = ex2f(sc);
        l += p;
        ull pp = pack2(p, p);
        const float* vr = &Vs[t2*16];
        ulonglong2 va = *(const ulonglong2*)&vr[0];
        ulonglong2 vb = *(const ulonglong2*)&vr[4];
        ulonglong2 vc = *(const ulonglong2*)&vr[8];
        ulonglong2 vd = *(const ulonglong2*)&vr[12];
        o[0] = ffma2(pp, va.x, o[0]);
        o[1] = ffma2(pp, va.y, o[1]);
        o[2] = ffma2(pp, vb.x, o[2]);
        o[3] = ffma2(pp, vb.y, o[3]);
        o[4] = ffma2(pp, vc.x, o[4]);
        o[5] = ffma2(pp, vc.y, o[5]);
        o[6] = ffma2(pp, vd.x, o[6]);
        o[7] = ffma2(pp, vd.y, o[7]);
    }
    float inv = 1.f / l;
    float of[16];
    #pragma unroll
    for (int c = 0; c < 8; c++) {
        unpack2(o[c], of[c*2], of[c*2+1]);
        of[c*2]   *= inv;
        of[c*2+1] *= inv;
    }
    __syncthreads();
    #pragma unroll
    for (int c = 0; c < 16; c += 4) {
        float4 ov = {of[c], of[c+1], of[c+2], of[c+3]};
        *(float4*)&Ks[s*16 + c] = ov;
    }
    __syncthreads();
    #pragma unroll
    for (int p = 0; p < 4; p++) {
        int i4 = p*512 + t;
        int tok = i4 >> 2, c4 = (i4 & 3) * 4;
        *(float4*)&out[(b*512 + tok)*128 + h*16 + c4] = *(const float4*)&Ks[tok*16 + c4];
    }
}

// ---------------- launch ----------------
extern "C" void kernel_launch(void* const* d_in, const int* in_sizes, int n_in,
                              void* d_out, int out_size) {
    const float* x     = (const float*)d_in[0];
    const int*   mask  = (const int*)  d_in[1];
    const float* ln_s  = (const float*)d_in[2];
    const float* ln_b  = (const float*)d_in[3];
    const float* dw_w  = (const float*)d_in[4];
    const float* dw_b  = (const float*)d_in[5];
    const float* pw_w  = (const float*)d_in[6];
    const float* pw_b  = (const float*)d_in[7];
    const float* Wq    = (const float*)d_in[8];
    const float* Wk    = (const float*)d_in[9];
    const float* Wv    = (const float*)d_in[10];
    const float* Wo    = (const float*)d_in[11];
    const float* ab    = (const float*)d_in[12];
    const float* f1w   = (const float*)d_in[13];
    const float* f1b   = (const float*)d_in[14];
    const float* f2w   = (const float*)d_in[15];
    const float* f2b   = (const float*)d_in[16];
    float* out = (float*)d_out;

    float *hA, *hB, *aP, *qkvP;
    u32* wBP;
    cudaGetSymbolAddress((void**)&hA,   g_h);
    cudaGetSymbolAddress((void**)&hB,   g_h2);
    cudaGetSymbolAddress((void**)&aP,   g_a);
    cudaGetSymbolAddress((void**)&qkvP, g_qkv);
    cudaGetSymbolAddress((void**)&wBP,  g_wB);

    const int GSMEM = (16384 + 8448) * 4;           // 99328 B
    const int ASMEM = (8192 + 8192 + 512) * 4;      // 66 KB

    auto gConv = gemmT<true,  false, 1, true,  true,  true>;
    auto gQKV  = gemmT<false, true,  2, false, false, false>;
    auto gWo   = gemmT<false, false, 2, false, true,  true>;
    auto gF1   = gemmT<false, false, 1, true,  false, false>;
    auto gF2   = gemmT<false, false, 1, false, true,  false>;
    cudaFuncSetAttribute(gConv, cudaFuncAttributeMaxDynamicSharedMemorySize, GSMEM);
    cudaFuncSetAttribute(gQKV,  cudaFuncAttributeMaxDynamicSharedMemorySize, GSMEM);
    cudaFuncSetAttribute(gWo,   cudaFuncAttributeMaxDynamicSharedMemorySize, GSMEM);
    cudaFuncSetAttribute(gF1,   cudaFuncAttributeMaxDynamicSharedMemorySize, GSMEM);
    cudaFuncSetAttribute(gF2,   cudaFuncAttributeMaxDynamicSharedMemorySize, GSMEM);
    cudaFuncSetAttribute(attnK, cudaFuncAttributeMaxDynamicSharedMemorySize, ASMEM);

    prep_weights<<<640, 256>>>(Wq, Wk, Wv, pw_w, f1w, f2w, Wo, wBP);
    addpos_ln<<<128, 512>>>(x, out, hA, ln_s, ln_b);

    float* hin = hA; float* hob = hB;
    for (int i = 0; i < 4; i++) {
        gConv<<<128, 256, GSMEM>>>(hin, wBP + (size_t)(3+i)*16384, pw_b + i*128, out, out, hob,
                                   ln_s + (i+1)*128, ln_b + (i+1)*128,
                                   dw_w + i*896, dw_b + i*128);
        float* tmp = hin; hin = hob; hob = tmp;
    }
    // hin holds LN[4](out)
    gQKV<<<dim3(128,3), 256, GSMEM>>>(hin, wBP, ab, nullptr, qkvP, nullptr,
                                      nullptr, nullptr, nullptr, nullptr);
    attnK<<<128, 512, ASMEM>>>(qkvP, mask, aP);
    gWo<<<128, 256, GSMEM>>>(aP, wBP + (size_t)9*16384, ab, out, out, hob,
                             ln_s + 5*128, ln_b + 5*128, nullptr, nullptr);
    gF1<<<128, 256, GSMEM>>>(hob, wBP + (size_t)7*16384, f1b, nullptr, aP, nullptr,
                             nullptr, nullptr, nullptr, nullptr);
    gF2<<<128, 256, GSMEM>>>(aP, wBP + (size_t)8*16384, f2b, out, out, nullptr,
                             nullptr, nullptr, nullptr, nullptr);
}

// round 7
// speedup vs baseline: 2.5638x; 1.1501x over previous
#include <cuda_runtime.h>
#include <cuda_bf16.h>
#include <math.h>

#define TOKS 8192
#define ELEMS 1048576
typedef unsigned long long ull;
typedef unsigned int u32;
typedef unsigned short u16;

// ---------------- scratch ----------------
__device__ float g_h[ELEMS];
__device__ float g_h2[ELEMS];
__device__ float g_a[ELEMS];
__device__ float g_qkv[3*ELEMS];
__device__ u32 g_wB[10*16384];      // weights in B-frag order, hi/lo split
__device__ u32 g_kvF[2*128*8192];   // K,V frags per (b,h): [mat][bh][part 2][...]

// ---------------- helpers ----------------
__device__ __forceinline__ u16 bfhi(float v) {
    return __bfloat16_as_ushort(__float2bfloat16_rn(v));
}
__device__ __forceinline__ float bf2f(u16 u) {
    return __bfloat162float(__ushort_as_bfloat16(u));
}
__device__ __forceinline__ float ex2f(float x) {
    float r; asm("ex2.approx.f32 %0, %1;" : "=f"(r) : "f"(x)); return r;
}
__device__ __forceinline__ u32 cvtbf2(float hi, float lo) {
    u32 r; asm("cvt.rn.bf16x2.f32 %0, %1, %2;" : "=r"(r) : "f"(hi), "f"(lo)); return r;
}
__device__ __forceinline__ void mma16816(float4& c, const uint4& a, const uint2& b) {
    asm("mma.sync.aligned.m16n8k16.row.col.f32.bf16.bf16.f32 "
        "{%0,%1,%2,%3}, {%4,%5,%6,%7}, {%8,%9}, {%0,%1,%2,%3};"
        : "+f"(c.x), "+f"(c.y), "+f"(c.z), "+f"(c.w)
        : "r"(a.x), "r"(a.y), "r"(a.z), "r"(a.w), "r"(b.x), "r"(b.y));
}
// split helpers: given f0,f1 produce hi-packed u32 and lo-packed u32
__device__ __forceinline__ void split2(float f0, float f1, u32& hi, u32& lo) {
    hi = cvtbf2(f1, f0);
    float h0 = __uint_as_float(hi << 16);
    float h1 = __uint_as_float(hi & 0xFFFF0000u);
    lo = cvtbf2(f1 - h1, f0 - h0);
}

// ---------------- weight prep (unchanged layout from R6) ----------------
__global__ void prep_weights(const float* __restrict__ Wq, const float* __restrict__ Wk,
                             const float* __restrict__ Wv, const float* __restrict__ pw,
                             const float* __restrict__ f1, const float* __restrict__ f2,
                             const float* __restrict__ Wo, u32* __restrict__ wB) {
    int idx = blockIdx.x*256 + threadIdx.x;          // 10*16384
    if (idx >= 10*16384) return;
    int j = idx >> 14, r = idx & 16383;
    int k = r >> 7, n = r & 127;
    float v;
    if (j < 3) {
        const float* W = (j==0) ? Wq : (j==1) ? Wk : Wv;   // (H,128,16)
        v = W[(n>>4)*2048 + k*16 + (n&15)];
    } else if (j < 7) {
        v = pw[(j-3)*16384 + n*128 + k];
    } else if (j < 9) {
        const float* W = (j==7) ? f1 : f2;
        v = W[n*128 + k];
    } else {
        v = Wo[k*128 + n];
    }
    u16 h = bfhi(v);
    u16 l = bfhi(v - bf2f(h));
    int kt = k >> 4, kk = k & 15;
    int reg = kk >> 3, tig = (kk & 7) >> 1, bb = kk & 1;
    int nt = n >> 3, lane = (n & 7)*4 + tig;
    u16* w16 = (u16*)(wB + (size_t)j*16384);
    int i32h = ((kt*16 + nt)*32 + lane)*2 + reg;
    int i32l = (((8 + kt)*16 + nt)*32 + lane)*2 + reg;
    w16[i32h*2 + bb] = h;
    w16[i32l*2 + bb] = l;
}

// ---------------- addpos + LN0 ----------------
__global__ __launch_bounds__(512) void addpos_ln(const float* __restrict__ x,
                                                 float* __restrict__ out, float* __restrict__ hout,
                                                 const float* __restrict__ lnS,
                                                 const float* __restrict__ lnB) {
    int m0 = blockIdx.x * 64;
    int lane = threadIdx.x & 31, warp = threadIdx.x >> 5;
    int col = lane * 4;
    const float inc = 0.14619588050756158f;   // log(10000)/63
    float4 g4 = *(const float4*)&lnS[col];
    float4 b4 = *(const float4*)&lnB[col];
    #pragma unroll
    for (int i = 0; i < 4; i++) {
        int m = m0 + warp*4 + i;
        int s = m & 511;
        float4 xv = *(const float4*)&x[m*128 + col];
        float v[4] = {xv.x, xv.y, xv.z, xv.w};
        #pragma unroll
        for (int jj = 0; jj < 4; jj++) {
            int d = col + jj;
            int dd = d & 63;
            float a = (float)s * expf(-inc*(float)dd);
            v[jj] += (d < 64) ? sinf(a) : cosf(a);
        }
        float rs_ = v[0]+v[1]+v[2]+v[3];
        float rq  = v[0]*v[0]+v[1]*v[1]+v[2]*v[2]+v[3]*v[3];
        #pragma unroll
        for (int o = 16; o > 0; o >>= 1) {
            rs_ += __shfl_xor_sync(0xffffffffu, rs_, o);
            rq  += __shfl_xor_sync(0xffffffffu, rq,  o);
        }
        float mu  = rs_ * (1.0f/128.0f);
        float var = rq  * (1.0f/128.0f) - mu*mu;
        float rinv = rsqrtf(var + 1e-5f);
        float4 ov = {v[0], v[1], v[2], v[3]};
        *(float4*)&out[m*128 + col] = ov;
        float4 hv;
        hv.x = (v[0]-mu)*rinv*g4.x + b4.x;
        hv.y = (v[1]-mu)*rinv*g4.y + b4.y;
        hv.z = (v[2]-mu)*rinv*g4.z + b4.z;
        hv.w = (v[3]-mu)*rinv*g4.w + b4.w;
        *(float4*)&hout[m*128 + col] = hv;
    }
}

// ---------------- tensor-core GEMM: 32xM tile, K=128, N=128, 256 thr ----------------
// smem: B32[16384] | union(A32[4096], Csm f32[32][132])
template<bool DW, bool MULTI, int BIASM, bool RELU, bool RES, bool LN>
__global__ __launch_bounds__(256) void gemmT(
    const float* __restrict__ A, const u32* __restrict__ Wf,
    const float* __restrict__ bias, const float* __restrict__ res,
    float* __restrict__ out, float* __restrict__ hout,
    const float* __restrict__ lnS, const float* __restrict__ lnB,
    const float* __restrict__ dww, const float* __restrict__ dwb)
{
    extern __shared__ u32 smu[];
    u32* B32 = smu;                     // 16384 u32
    u32* A32 = smu + 16384;             // 4096 u32
    float* Csm = (float*)(smu + 16384); // 32 x 132 f32 (4224)
    if (MULTI) { Wf += blockIdx.y * 16384; out += (size_t)blockIdx.y * ELEMS; }

    int m0 = blockIdx.x * 32;
    int t = threadIdx.x, lane = t & 31, warp = t >> 5;

    #pragma unroll
    for (int i = 0; i < 16; i++)
        *(uint4*)&B32[i*1024 + t*4] = *(const uint4*)&Wf[i*1024 + t*4];

    u16* A16 = (u16*)A32;
    if (DW) {
        int d = t & 127, q = t >> 7;       // q in {0,1}, 16 tokens each
        float wr[7];
        #pragma unroll
        for (int kk = 0; kk < 7; kk++) wr[kk] = dww[d*7 + kk];
        float db = dwb[d];
        int kt = d >> 4;
        int tig = (d & 7) >> 1, bb = d & 1;
        int kreg2 = ((d & 15) >> 3) * 2;
        const float* hb = A + (size_t)(m0 & ~511) * 128;
        int sBase = (m0 & 511) + q*16;
        float hwin[22];
        #pragma unroll
        for (int jj = 0; jj < 22; jj++) {
            int s = sBase + jj - 3;
            hwin[jj] = (s >= 0 && s < 512) ? hb[s*128 + d] : 0.f;
        }
        #pragma unroll
        for (int i = 0; i < 16; i++) {
            float acc = db;
            #pragma unroll
            for (int kk = 0; kk < 7; kk++) acc += wr[kk] * hwin[i+kk];
            int ml = q*16 + i;
            int mt = ml >> 4, mm = ml & 15;
            int g = mm & 7, hi8 = mm >> 3;
            int reg = hi8 + kreg2;
            int ln2 = g*4 + tig;
            u16 h = bfhi(acc);
            u16 l = bfhi(acc - bf2f(h));
            int ih = ((mt*8 + kt)*32 + ln2)*4 + reg;
            int il = (((2 + mt)*8 + kt)*32 + ln2)*4 + reg;
            A16[ih*2 + bb] = h;
            A16[il*2 + bb] = l;
        }
    } else {
        #pragma unroll
        for (int i = 0; i < 4; i++) {
            int idx4 = i*256 + t;
            int m = idx4 >> 5;                  // 0..31
            int k0 = (idx4 & 31) * 4;
            float4 v = *(const float4*)&A[(size_t)(m0 + m)*128 + k0];
            float vv[4] = {v.x, v.y, v.z, v.w};
            int mt = m >> 4, mm = m & 15;
            int g = mm & 7, hi8 = mm >> 3;
            int kt = k0 >> 4;
            #pragma unroll
            for (int j = 0; j < 4; j += 2) {
                int k = k0 + j;
                int tig = (k & 7) >> 1;
                int reg = hi8 + 2*((k & 15) >> 3);
                int ln2 = g*4 + tig;
                u32 hi, lo;
                split2(vv[j], vv[j+1], hi, lo);
                A32[((mt*8 + kt)*32 + ln2)*4 + reg]     = hi;
                A32[(((2+mt)*8 + kt)*32 + ln2)*4 + reg] = lo;
            }
        }
    }
    __syncthreads();

    // mainloop: warp = (wm in 0..1, wn in 0..3): 1 m-tile x 4 n-tiles
    int wm = warp >> 2, wn = warp & 3;
    int nt0 = wn*4;
    float4 acc[4];
    #pragma unroll
    for (int j = 0; j < 4; j++) acc[j] = make_float4(0.f,0.f,0.f,0.f);

    #pragma unroll
    for (int kt = 0; kt < 8; kt++) {
        uint4 ah = *(const uint4*)&A32[((wm*8 + kt)*32 + lane)*4];
        uint4 al = *(const uint4*)&A32[(((2+wm)*8 + kt)*32 + lane)*4];
        uint2 bh[4], bl[4];
        #pragma unroll
        for (int j = 0; j < 4; j++) {
            bh[j] = *(const uint2*)&B32[((kt*16 + nt0+j)*32 + lane)*2];
            bl[j] = *(const uint2*)&B32[(((8+kt)*16 + nt0+j)*32 + lane)*2];
        }
        #pragma unroll
        for (int j = 0; j < 4; j++) {
            mma16816(acc[j], ah, bh[j]);
            mma16816(acc[j], ah, bl[j]);
            mma16816(acc[j], al, bh[j]);
        }
    }
    __syncthreads();

    #pragma unroll
    for (int j = 0; j < 4; j++) {
        int row = wm*16 + (lane >> 2);
        int col = (nt0+j)*8 + (lane & 3)*2;
        float2 lo = {acc[j].x, acc[j].y};
        float2 hi = {acc[j].z, acc[j].w};
        *(float2*)&Csm[row*132 + col]     = lo;
        *(float2*)&Csm[(row+8)*132 + col] = hi;
    }
    __syncthreads();

    int colE = lane*4;
    float4 bv = {0,0,0,0};
    if (BIASM == 1) bv = *(const float4*)&bias[colE];
    float bs = (BIASM == 2) ? bias[0] : 0.f;
    float4 g4 = {0,0,0,0}, lb4 = {0,0,0,0};
    if (LN) { g4 = *(const float4*)&lnS[colE]; lb4 = *(const float4*)&lnB[colE]; }

    #pragma unroll
    for (int i = 0; i < 4; i++) {
        int row = warp*4 + i;
        int m = m0 + row;
        float4 c4 = *(const float4*)&Csm[row*132 + colE];
        float v[4] = {c4.x, c4.y, c4.z, c4.w};
        #pragma unroll
        for (int jj = 0; jj < 4; jj++) {
            float val = v[jj];
            if (BIASM == 1) val += ((const float*)&bv)[jj];
            if (BIASM == 2) val += bs;
            if (RELU) val = fmaxf(val, 0.f);
            v[jj] = val;
        }
        if (RES) {
            float4 r4 = *(const float4*)&res[(size_t)m*128 + colE];
            v[0] += r4.x; v[1] += r4.y; v[2] += r4.z; v[3] += r4.w;
        }
        float4 ov = {v[0], v[1], v[2], v[3]};
        *(float4*)&out[(size_t)m*128 + colE] = ov;
        if (LN) {
            float rs_ = v[0]+v[1]+v[2]+v[3];
            float rq  = v[0]*v[0]+v[1]*v[1]+v[2]*v[2]+v[3]*v[3];
            #pragma unroll
            for (int o = 16; o > 0; o >>= 1) {
                rs_ += __shfl_xor_sync(0xffffffffu, rs_, o);
                rq  += __shfl_xor_sync(0xffffffffu, rq,  o);
            }
            float mu  = rs_ * (1.0f/128.0f);
            float var = rq  * (1.0f/128.0f) - mu*mu;
            float rinv = rsqrtf(var + 1e-5f);
            float4 hv;
            hv.x = (v[0]-mu)*rinv*g4.x + lb4.x;
            hv.y = (v[1]-mu)*rinv*g4.y + lb4.y;
            hv.z = (v[2]-mu)*rinv*g4.z + lb4.z;
            hv.w = (v[3]-mu)*rinv*g4.w + lb4.w;
            *(float4*)&hout[(size_t)m*128 + colE] = hv;
        }
    }
}

// ---------------- repack K,V into mma B-fragments (hi/lo split) ----------------
// K frags per bh: [part2][nt 64][lane 32][reg 2]  (n=key, k=dim)
// V frags per bh: [part2][kt 32][nt 2][lane 32][reg 2]  (k=key, n=dim)
__global__ __launch_bounds__(256) void kvRepack(const float* __restrict__ qkv,
                                                u32* __restrict__ kvF) {
    __shared__ u32 st[8192];
    int mat = blockIdx.x;                 // 0=K, 1=V
    int bh = blockIdx.y;
    int b = bh >> 3, h = bh & 7;
    const float* src = qkv + (size_t)(1 + mat)*ELEMS;
    int t = threadIdx.x;
    int key0 = t*2;

    float v0[16], v1[16];
    const float* p0 = src + (size_t)(b*512 + key0)*128 + h*16;
    const float* p1 = p0 + 128;
    #pragma unroll
    for (int i = 0; i < 4; i++) {
        *(float4*)&v0[i*4] = *(const float4*)(p0 + i*4);
        *(float4*)&v1[i*4] = *(const float4*)(p1 + i*4);
    }

    if (mat == 0) {
        #pragma unroll
        for (int w = 0; w < 2; w++) {
            const float* vv = (w == 0) ? v0 : v1;
            int key = key0 + w;
            int nt = key >> 3;
            int laneb = (key & 7)*4;
            #pragma unroll
            for (int dp = 0; dp < 8; dp++) {
                int tig = dp & 3, reg = dp >> 2;
                u32 hi, lo;
                split2(vv[2*dp], vv[2*dp+1], hi, lo);
                int idx = ((nt*32) + laneb + tig)*2 + reg;
                st[idx] = hi; st[4096 + idx] = lo;
            }
        }
    } else {
        int kt = key0 >> 4;
        int tig = (key0 >> 1) & 3;
        int reg = (key0 & 15) >> 3;
        #pragma unroll
        for (int d = 0; d < 16; d++) {
            u32 hi, lo;
            split2(v0[d], v1[d], hi, lo);    // packs (key even, key odd)
            int nt = d >> 3, nn = d & 7;
            int idx = ((kt*2 + nt)*32 + nn*4 + tig)*2 + reg;
            st[idx] = hi; st[4096 + idx] = lo;
        }
    }
    __syncthreads();
    u32* dst = kvF + (size_t)(mat*128 + bh)*8192;
    #pragma unroll
    for (int i = 0; i < 8; i++)
        *(uint4*)&dst[i*1024 + t*4] = *(const uint4*)&st[i*1024 + t*4];
}

// ---------------- tensor-core flash attention ----------------
// grid (4 qtiles, 128 bh), 128 threads (4 warps); warp owns 32 q rows (2 m-tiles)
__global__ __launch_bounds__(128) void attnT(const float* __restrict__ qkv,
                                             const u32* __restrict__ kvF,
                                             const int* __restrict__ mask,
                                             float* __restrict__ out) {
    __shared__ float Ms[512];
    int bh = blockIdx.y;
    int b = bh >> 3, h = bh & 7;
    int qbase = blockIdx.x * 128;
    int t = threadIdx.x, lane = t & 31, warp = t >> 5;
    int c2 = (lane & 3)*2;

    #pragma unroll
    for (int i = 0; i < 4; i++) {
        int key = i*128 + t;
        Ms[key] = mask[b*512 + key] ? 0.f : -1e30f;
    }
    __syncthreads();

    const u32* Kf = kvF + (size_t)bh * 8192;
    const u32* Vf = kvF + (size_t)(128 + bh) * 8192;

    // Q A-frags (2 m-tiles), pre-scaled, hi/lo split
    const float qsc = 0.25f * 1.4426950408889634f;
    uint4 qh[2], ql[2];
    #pragma unroll
    for (int i = 0; i < 2; i++) {
        int r = qbase + warp*32 + i*16 + (lane >> 2);
        const float* b0p = qkv + (size_t)(b*512 + r)*128 + h*16;
        const float* b1p = b0p + 8*128;
        float2 fa = *(const float2*)(b0p + c2);
        float2 fc = *(const float2*)(b0p + c2 + 8);
        float2 fb = *(const float2*)(b1p + c2);
        float2 fd = *(const float2*)(b1p + c2 + 8);
        fa.x *= qsc; fa.y *= qsc; fb.x *= qsc; fb.y *= qsc;
        fc.x *= qsc; fc.y *= qsc; fd.x *= qsc; fd.y *= qsc;
        split2(fa.x, fa.y, qh[i].x, ql[i].x);
        split2(fb.x, fb.y, qh[i].y, ql[i].y);
        split2(fc.x, fc.y, qh[i].z, ql[i].z);
        split2(fd.x, fd.y, qh[i].w, ql[i].w);
    }

    float4 oAcc[2][2];
    float lAcc[2][2];
    #pragma unroll
    for (int i = 0; i < 2; i++) {
        oAcc[i][0] = make_float4(0,0,0,0);
        oAcc[i][1] = make_float4(0,0,0,0);
        lAcc[i][0] = 0.f; lAcc[i][1] = 0.f;
    }

    for (int kb = 0; kb < 8; kb++) {
        #pragma unroll
        for (int ktl = 0; ktl < 4; ktl++) {
            int nt0 = kb*8 + ktl*2;
            uint2 kh0 = *(const uint2*)&Kf[(nt0*32 + lane)*2];
            uint2 kh1 = *(const uint2*)&Kf[((nt0+1)*32 + lane)*2];
            uint2 kl0 = *(const uint2*)&Kf[4096 + (nt0*32 + lane)*2];
            uint2 kl1 = *(const uint2*)&Kf[4096 + ((nt0+1)*32 + lane)*2];

            float4 s[2][2];
            #pragma unroll
            for (int i = 0; i < 2; i++) {
                s[i][0] = make_float4(0,0,0,0);
                s[i][1] = make_float4(0,0,0,0);
                mma16816(s[i][0], qh[i], kh0);
                mma16816(s[i][0], ql[i], kh0);
                mma16816(s[i][0], qh[i], kl0);
                mma16816(s[i][1], qh[i], kh1);
                mma16816(s[i][1], ql[i], kh1);
                mma16816(s[i][1], qh[i], kl1);
            }

            int colb = nt0*8 + c2;
            float m00 = Ms[colb],     m01 = Ms[colb+1];
            float m10 = Ms[colb+8],   m11 = Ms[colb+9];

            uint4 pah[2], pal[2];
            #pragma unroll
            for (int i = 0; i < 2; i++) {
                float px0 = ex2f(s[i][0].x + m00);
                float py0 = ex2f(s[i][0].y + m01);
                float pz0 = ex2f(s[i][0].z + m00);
                float pw0 = ex2f(s[i][0].w + m01);
                float px1 = ex2f(s[i][1].x + m10);
                float py1 = ex2f(s[i][1].y + m11);
                float pz1 = ex2f(s[i][1].z + m10);
                float pw1 = ex2f(s[i][1].w + m11);
                lAcc[i][0] += px0 + py0 + px1 + py1;
                lAcc[i][1] += pz0 + pw0 + pz1 + pw1;
                split2(px0, py0, pah[i].x, pal[i].x);
                split2(pz0, pw0, pah[i].y, pal[i].y);
                split2(px1, py1, pah[i].z, pal[i].z);
                split2(pz1, pw1, pah[i].w, pal[i].w);
            }

            int ktg = kb*4 + ktl;
            uint2 vh0 = *(const uint2*)&Vf[((ktg*2 + 0)*32 + lane)*2];
            uint2 vh1 = *(const uint2*)&Vf[((ktg*2 + 1)*32 + lane)*2];
            uint2 vl0 = *(const uint2*)&Vf[4096 + ((ktg*2 + 0)*32 + lane)*2];
            uint2 vl1 = *(const uint2*)&Vf[4096 + ((ktg*2 + 1)*32 + lane)*2];
            #pragma unroll
            for (int i = 0; i < 2; i++) {
                mma16816(oAcc[i][0], pah[i], vh0);
                mma16816(oAcc[i][0], pal[i], vh0);
                mma16816(oAcc[i][0], pah[i], vl0);
                mma16816(oAcc[i][1], pah[i], vh1);
                mma16816(oAcc[i][1], pal[i], vh1);
                mma16816(oAcc[i][1], pah[i], vl1);
            }
        }
    }

    // row-sum reduce across the 4 lanes sharing a row
    #pragma unroll
    for (int i = 0; i < 2; i++)
        #pragma unroll
        for (int j = 0; j < 2; j++) {
            lAcc[i][j] += __shfl_xor_sync(0xffffffffu, lAcc[i][j], 1);
            lAcc[i][j] += __shfl_xor_sync(0xffffffffu, lAcc[i][j], 2);
        }

    #pragma unroll
    for (int i = 0; i < 2; i++) {
        float inv0 = 1.f / lAcc[i][0];
        float inv1 = 1.f / lAcc[i][1];
        int r = qbase + warp*32 + i*16 + (lane >> 2);
        #pragma unroll
        for (int n = 0; n < 2; n++) {
            float* op = out + (size_t)(b*512 + r)*128 + h*16 + n*8 + c2;
            float2 lo = {oAcc[i][n].x * inv0, oAcc[i][n].y * inv0};
            float2 hi = {oAcc[i][n].z * inv1, oAcc[i][n].w * inv1};
            *(float2*)op = lo;
            *(float2*)(op + 8*128) = hi;
        }
    }
}

// ---------------- launch ----------------
extern "C" void kernel_launch(void* const* d_in, const int* in_sizes, int n_in,
                              void* d_out, int out_size) {
    const float* x     = (const float*)d_in[0];
    const int*   mask  = (const int*)  d_in[1];
    const float* ln_s  = (const float*)d_in[2];
    const float* ln_b  = (const float*)d_in[3];
    const float* dw_w  = (const float*)d_in[4];
    const float* dw_b  = (const float*)d_in[5];
    const float* pw_w  = (const float*)d_in[6];
    const float* pw_b  = (const float*)d_in[7];
    const float* Wq    = (const float*)d_in[8];
    const float* Wk    = (const float*)d_in[9];
    const float* Wv    = (const float*)d_in[10];
    const float* Wo    = (const float*)d_in[11];
    const float* ab    = (const float*)d_in[12];
    const float* f1w   = (const float*)d_in[13];
    const float* f1b   = (const float*)d_in[14];
    const float* f2w   = (const float*)d_in[15];
    const float* f2b   = (const float*)d_in[16];
    float* out = (float*)d_out;

    float *hA, *hB, *aP, *qkvP;
    u32 *wBP, *kvFP;
    cudaGetSymbolAddress((void**)&hA,   g_h);
    cudaGetSymbolAddress((void**)&hB,   g_h2);
    cudaGetSymbolAddress((void**)&aP,   g_a);
    cudaGetSymbolAddress((void**)&qkvP, g_qkv);
    cudaGetSymbolAddress((void**)&wBP,  g_wB);
    cudaGetSymbolAddress((void**)&kvFP, g_kvF);

    const int GSMEM = (16384 + 4224) * 4;           // 82432 B

    auto gConv = gemmT<true,  false, 1, true,  true,  true>;
    auto gQKV  = gemmT<false, true,  2, false, false, false>;
    auto gWo   = gemmT<false, false, 2, false, true,  true>;
    auto gF1   = gemmT<false, false, 1, true,  false, false>;
    auto gF2   = gemmT<false, false, 1, false, true,  false>;
    cudaFuncSetAttribute(gConv, cudaFuncAttributeMaxDynamicSharedMemorySize, GSMEM);
    cudaFuncSetAttribute(gQKV,  cudaFuncAttributeMaxDynamicSharedMemorySize, GSMEM);
    cudaFuncSetAttribute(gWo,   cudaFuncAttributeMaxDynamicSharedMemorySize, GSMEM);
    cudaFuncSetAttribute(gF1,   cudaFuncAttributeMaxDynamicSharedMemorySize, GSMEM);
    cudaFuncSetAttribute(gF2,   cudaFuncAttributeMaxDynamicSharedMemorySize, GSMEM);

    prep_weights<<<640, 256>>>(Wq, Wk, Wv, pw_w, f1w, f2w, Wo, wBP);
    addpos_ln<<<128, 512>>>(x, out, hA, ln_s, ln_b);

    float* hin = hA; float* hob = hB;
    for (int i = 0; i < 4; i++) {
        gConv<<<256, 256, GSMEM>>>(hin, wBP + (size_t)(3+i)*16384, pw_b + i*128, out, out, hob,
                                   ln_s + (i+1)*128, ln_b + (i+1)*128,
                                   dw_w + i*896, dw_b + i*128);
        float* tmp = hin; hin = hob; hob = tmp;
    }
    // hin holds LN[4](out)
    gQKV<<<dim3(256,3), 256, GSMEM>>>(hin, wBP, ab, nullptr, qkvP, nullptr,
                                      nullptr, nullptr, nullptr, nullptr);
    kvRepack<<<dim3(2,128), 256>>>(qkvP, kvFP);
    attnT<<<dim3(4,128), 128>>>(qkvP, kvFP, mask, aP);
    gWo<<<256, 256, GSMEM>>>(aP, wBP + (size_t)9*16384, ab, out, out, hob,
                             ln_s + 5*128, ln_b + 5*128, nullptr, nullptr);
    gF1<<<256, 256, GSMEM>>>(hob, wBP + (size_t)7*16384, f1b, nullptr, aP, nullptr,
                             nullptr, nullptr, nullptr, nullptr);
    gF2<<<256, 256, GSMEM>>>(aP, wBP + (size_t)8*16384, f2b, out, out, nullptr,
                             nullptr, nullptr, nullptr, nullptr);
}